// round 8
// baseline (speedup 1.0000x reference)
#include <cuda_runtime.h>
#include <math_constants.h>

// ---------------- problem constants ----------------
#define NN 100000      // nodes
#define NE 3200000     // edges
#define NG 512         // graphs
#define BN_EPS 1e-5f
#define NBLK ((NN + 255) / 256)   // 391

// ---------------- device scratch (no allocs allowed) ----------------
__device__ int      d_cnt[NN];
__device__ int      d_rowptr[NN + 1];
__device__ int      d_wp[NN];
__device__ int      d_bsum[512];
__device__ int      d_boff[512];
__device__ float2   d_csr[NE];            // (src as int bits, norm)
__device__ float    d_dis[NN];
__device__ float    d_y1 [(size_t)NN * 8];
__device__ float    d_y2 [(size_t)NN * 32];
__device__ float    d_y3 [(size_t)NN * 128];
__device__ float    d_stats[256];         // zero at load; reset after each use
__device__ float    d_scale[128];
__device__ float    d_shift[128];
__device__ int      d_gstart[NG];
__device__ int      d_gend[NG];
__device__ int      d_is64_edge;
__device__ int      d_is64_batch;
__device__ int      d_tick;               // zero at load; reset by last block

// ---------------- dtype detection (parallel: 1 load per thread) ----------------
__global__ void k_detect(const void* ei, const void* bi) {
    int t = threadIdx.x;
    if (blockIdx.x == 0) {
        long long v = ((const long long*)ei)[(size_t)t * 6000];
        int ok = (v >= 0 && v < NN);
        ok = __syncthreads_and(ok);
        if (t == 0) d_is64_edge = ok;
    } else {
        long long v = ((const long long*)bi)[(size_t)t * 195];
        int ok = (v >= 0 && v < NG);
        ok = __syncthreads_and(ok);
        if (t == 0) d_is64_batch = ok;
    }
}

// ---------------- init counters + graph boundaries (batch sorted) ----------------
__global__ void k_initbounds(const void* bi) {
    int i = blockIdx.x * blockDim.x + threadIdx.x;
    if (i >= NN) return;
    d_cnt[i] = 0;
    int g, gp, gn;
    if (d_is64_batch) {
        const long long* p = (const long long*)bi;
        g  = (int)p[i];
        gp = (i > 0)      ? (int)p[i - 1] : -1;
        gn = (i < NN - 1) ? (int)p[i + 1] : NG;
    } else {
        const int* p = (const int*)bi;
        g  = p[i];
        gp = (i > 0)      ? p[i - 1] : -1;
        gn = (i < NN - 1) ? p[i + 1] : NG;
    }
    if (g != gp) d_gstart[g] = i;
    if (g != gn) d_gend[g] = i + 1;
}

// ---------------- CSR build ----------------
__global__ void k_count(const void* ei) {
    int e = blockIdx.x * blockDim.x + threadIdx.x;
    if (e >= NE) return;
    int d;
    if (d_is64_edge) d = (int)((const long long*)ei)[(size_t)NE + e];
    else             d = ((const int*)ei)[NE + e];
    atomicAdd(&d_cnt[d], 1);
}

__global__ void k_scan1() {
    __shared__ int s[256];
    int i = blockIdx.x * 256 + threadIdx.x;
    int v = (i < NN) ? d_cnt[i] : 0;
    s[threadIdx.x] = v;
    __syncthreads();
    for (int o = 128; o > 0; o >>= 1) {
        if (threadIdx.x < o) s[threadIdx.x] += s[threadIdx.x + o];
        __syncthreads();
    }
    if (threadIdx.x == 0) d_bsum[blockIdx.x] = s[0];
}

__global__ void k_scan2() {
    __shared__ int s[512];
    int t = threadIdx.x;
    int orig = (t < NBLK) ? d_bsum[t] : 0;
    s[t] = orig;
    __syncthreads();
    for (int o = 1; o < 512; o <<= 1) {
        int u = (t >= o) ? s[t - o] : 0;
        __syncthreads();
        s[t] += u;
        __syncthreads();
    }
    d_boff[t] = s[t] - orig;
}

__global__ void k_scan3() {
    __shared__ int s[256];
    int i = blockIdx.x * 256 + threadIdx.x;
    int orig = (i < NN) ? d_cnt[i] : 0;
    s[threadIdx.x] = orig;
    __syncthreads();
    for (int o = 1; o < 256; o <<= 1) {
        int u = (threadIdx.x >= o) ? s[threadIdx.x - o] : 0;
        __syncthreads();
        s[threadIdx.x] += u;
        __syncthreads();
    }
    int excl = s[threadIdx.x] - orig + d_boff[blockIdx.x];
    if (i < NN) {
        d_rowptr[i] = excl;
        d_wp[i] = excl;
        d_dis[i] = rsqrtf((float)(orig + 1));
    }
    if (i == 0) d_rowptr[NN] = NE;
}

__global__ void k_fill(const void* ei) {
    int e = blockIdx.x * blockDim.x + threadIdx.x;
    if (e >= NE) return;
    int s, d;
    if (d_is64_edge) {
        const long long* p = (const long long*)ei;
        s = (int)p[e];
        d = (int)p[(size_t)NE + e];
    } else {
        const int* p = (const int*)ei;
        s = p[e];
        d = p[NE + e];
    }
    int pos = atomicAdd(&d_wp[d], 1);
    d_csr[pos] = make_float2(__int_as_float(s), d_dis[s] * d_dis[d]);
}

// ---------------- layer 1 fused: agg(F=2) + GEMM 2->8 + relu ----------------
__global__ void k_l1(const float* __restrict__ x,
                     const float* __restrict__ W1, const float* __restrict__ b1) {
    __shared__ float sW[16], sb[8];
    if (threadIdx.x < 16) sW[threadIdx.x] = W1[threadIdx.x];
    if (threadIdx.x < 8)  sb[threadIdx.x] = b1[threadIdx.x];
    __syncthreads();
    int i = blockIdx.x * blockDim.x + threadIdx.x;
    if (i >= NN) return;
    const float2* x2 = (const float2*)x;
    float di = d_dis[i];
    float2 self = x2[i];
    float ax = self.x * di * di, ay = self.y * di * di;
    int e = d_rowptr[i], end = d_rowptr[i + 1];
    for (; e + 4 <= end; e += 4) {
        float2 p0 = __ldg(&d_csr[e]),     p1 = __ldg(&d_csr[e + 1]);
        float2 p2 = __ldg(&d_csr[e + 2]), p3 = __ldg(&d_csr[e + 3]);
        float2 v0 = __ldg(&x2[__float_as_int(p0.x)]);
        float2 v1 = __ldg(&x2[__float_as_int(p1.x)]);
        float2 v2 = __ldg(&x2[__float_as_int(p2.x)]);
        float2 v3 = __ldg(&x2[__float_as_int(p3.x)]);
        ax += v0.x * p0.y + v1.x * p1.y + v2.x * p2.y + v3.x * p3.y;
        ay += v0.y * p0.y + v1.y * p1.y + v2.y * p2.y + v3.y * p3.y;
    }
    for (; e < end; e++) {
        float2 p = __ldg(&d_csr[e]);
        float2 v = __ldg(&x2[__float_as_int(p.x)]);
        ax += v.x * p.y;
        ay += v.y * p.y;
    }
    float4 o0, o1;
    o0.x = fmaxf(ax * sW[0] + ay * sW[8]  + sb[0], 0.f);
    o0.y = fmaxf(ax * sW[1] + ay * sW[9]  + sb[1], 0.f);
    o0.z = fmaxf(ax * sW[2] + ay * sW[10] + sb[2], 0.f);
    o0.w = fmaxf(ax * sW[3] + ay * sW[11] + sb[3], 0.f);
    o1.x = fmaxf(ax * sW[4] + ay * sW[12] + sb[4], 0.f);
    o1.y = fmaxf(ax * sW[5] + ay * sW[13] + sb[5], 0.f);
    o1.z = fmaxf(ax * sW[6] + ay * sW[14] + sb[6], 0.f);
    o1.w = fmaxf(ax * sW[7] + ay * sW[15] + sb[7], 0.f);
    float4* yo = (float4*)(d_y1 + (size_t)i * 8);
    yo[0] = o0;
    yo[1] = o1;
}

// ---------------- layer 2 fused: agg(F=8, BN folded) + GEMM 8->32 + relu ----------------
__global__ void k_l2(const float* __restrict__ W2, const float* __restrict__ b2) {
    __shared__ float sW[8 * 32], sb[32];
    for (int k = threadIdx.x; k < 256; k += blockDim.x) sW[k] = W2[k];
    if (threadIdx.x < 32) sb[threadIdx.x] = b2[threadIdx.x];
    __syncthreads();
    int lane = threadIdx.x & 31;
    int sub  = lane >> 3;
    int ln   = lane & 7;
    int gwarp  = (blockIdx.x * blockDim.x + threadIdx.x) >> 5;
    int nwarps = (gridDim.x * blockDim.x) >> 5;
    float sc = d_scale[ln], sh = d_shift[ln];
    for (int n0 = gwarp * 4; n0 < NN; n0 += nwarps * 4) {
        int node = n0 + sub;
        bool act = node < NN;
        int e = 0, end = 0;
        float acc = 0.f;
        if (act) {
            float di = d_dis[node];
            e = d_rowptr[node];
            end = d_rowptr[node + 1];
            acc = fmaf(d_y1[(size_t)node * 8 + ln], sc, sh) * di * di;
        }
        for (; e + 4 <= end; e += 4) {
            float2 p0 = __ldg(&d_csr[e]),     p1 = __ldg(&d_csr[e + 1]);
            float2 p2 = __ldg(&d_csr[e + 2]), p3 = __ldg(&d_csr[e + 3]);
            float h0 = __ldg(&d_y1[(size_t)__float_as_int(p0.x) * 8 + ln]);
            float h1 = __ldg(&d_y1[(size_t)__float_as_int(p1.x) * 8 + ln]);
            float h2 = __ldg(&d_y1[(size_t)__float_as_int(p2.x) * 8 + ln]);
            float h3 = __ldg(&d_y1[(size_t)__float_as_int(p3.x) * 8 + ln]);
            acc = fmaf(fmaf(h0, sc, sh), p0.y, acc);
            acc = fmaf(fmaf(h1, sc, sh), p1.y, acc);
            acc = fmaf(fmaf(h2, sc, sh), p2.y, acc);
            acc = fmaf(fmaf(h3, sc, sh), p3.y, acc);
        }
        for (; e < end; e++) {
            float2 p = __ldg(&d_csr[e]);
            float hv = __ldg(&d_y1[(size_t)__float_as_int(p.x) * 8 + ln]);
            acc = fmaf(fmaf(hv, sc, sh), p.y, acc);
        }
        float4 yv = make_float4(sb[ln * 4], sb[ln * 4 + 1], sb[ln * 4 + 2], sb[ln * 4 + 3]);
#pragma unroll
        for (int f = 0; f < 8; f++) {
            float av = __shfl_sync(0xFFFFFFFFu, acc, f, 8);
            const float* wr = &sW[f * 32 + ln * 4];
            yv.x = fmaf(av, wr[0], yv.x);
            yv.y = fmaf(av, wr[1], yv.y);
            yv.z = fmaf(av, wr[2], yv.z);
            yv.w = fmaf(av, wr[3], yv.w);
        }
        yv.x = fmaxf(yv.x, 0.f); yv.y = fmaxf(yv.y, 0.f);
        yv.z = fmaxf(yv.z, 0.f); yv.w = fmaxf(yv.w, 0.f);
        if (act) ((float4*)(d_y2 + (size_t)node * 32))[ln] = yv;
    }
}

// ---------------- layer 3 fused: agg(F=32, BN folded) + GEMM 32->128 + relu ----------------
__global__ void k_l3(const float* __restrict__ W3, const float* __restrict__ b3) {
    __shared__ float4 sW4[32 * 32];
    __shared__ float  sb[128];
    for (int k = threadIdx.x; k < 1024; k += blockDim.x)
        sW4[k] = ((const float4*)W3)[k];
    if (threadIdx.x < 128) sb[threadIdx.x] = b3[threadIdx.x];
    __syncthreads();
    int lane = threadIdx.x & 31;
    int gwarp  = (blockIdx.x * blockDim.x + threadIdx.x) >> 5;
    int nwarps = (gridDim.x * blockDim.x) >> 5;
    float sc = d_scale[lane], sh = d_shift[lane];
    for (int node = gwarp; node < NN; node += nwarps) {
        float di = d_dis[node];
        int e = d_rowptr[node], end = d_rowptr[node + 1];
        float acc = fmaf(d_y2[(size_t)node * 32 + lane], sc, sh) * di * di;
        for (; e + 4 <= end; e += 4) {
            float2 p0 = __ldg(&d_csr[e]),     p1 = __ldg(&d_csr[e + 1]);
            float2 p2 = __ldg(&d_csr[e + 2]), p3 = __ldg(&d_csr[e + 3]);
            float h0 = __ldg(&d_y2[(size_t)__float_as_int(p0.x) * 32 + lane]);
            float h1 = __ldg(&d_y2[(size_t)__float_as_int(p1.x) * 32 + lane]);
            float h2 = __ldg(&d_y2[(size_t)__float_as_int(p2.x) * 32 + lane]);
            float h3 = __ldg(&d_y2[(size_t)__float_as_int(p3.x) * 32 + lane]);
            acc = fmaf(fmaf(h0, sc, sh), p0.y, acc);
            acc = fmaf(fmaf(h1, sc, sh), p1.y, acc);
            acc = fmaf(fmaf(h2, sc, sh), p2.y, acc);
            acc = fmaf(fmaf(h3, sc, sh), p3.y, acc);
        }
        for (; e < end; e++) {
            float2 p = __ldg(&d_csr[e]);
            float hv = __ldg(&d_y2[(size_t)__float_as_int(p.x) * 32 + lane]);
            acc = fmaf(fmaf(hv, sc, sh), p.y, acc);
        }
        float4 yv = make_float4(sb[lane * 4], sb[lane * 4 + 1],
                                sb[lane * 4 + 2], sb[lane * 4 + 3]);
#pragma unroll
        for (int f = 0; f < 32; f++) {
            float av = __shfl_sync(0xFFFFFFFFu, acc, f);
            float4 w = sW4[f * 32 + lane];
            yv.x = fmaf(av, w.x, yv.x);
            yv.y = fmaf(av, w.y, yv.y);
            yv.z = fmaf(av, w.z, yv.z);
            yv.w = fmaf(av, w.w, yv.w);
        }
        yv.x = fmaxf(yv.x, 0.f); yv.y = fmaxf(yv.y, 0.f);
        yv.z = fmaxf(yv.z, 0.f); yv.w = fmaxf(yv.w, 0.f);
        ((float4*)(d_y3 + (size_t)node * 128))[lane] = yv;
    }
}

// ---------------- BN stats + fused params (last-block epilogue) ----------------
template <int FO>
__global__ void k_stats(const float* __restrict__ y,
                        const float* __restrict__ gam,
                        const float* __restrict__ bet) {
    constexpr int R = 256 / FO;
    __shared__ float ssum[256], ssq[256];
    int c = threadIdx.x % FO;
    int r = threadIdx.x / FO;
    float s = 0.f, q = 0.f;
    for (int i = blockIdx.x * R + r; i < NN; i += gridDim.x * R) {
        float v = y[(size_t)i * FO + c];
        s += v;
        q += v * v;
    }
    ssum[threadIdx.x] = s;
    ssq[threadIdx.x] = q;
    __syncthreads();
    if (r == 0) {
#pragma unroll
        for (int k = 1; k < R; k++) {
            s += ssum[k * FO + c];
            q += ssq[k * FO + c];
        }
        atomicAdd(&d_stats[c], s);
        atomicAdd(&d_stats[128 + c], q);
    }
    __threadfence();
    __shared__ int isLast;
    if (threadIdx.x == 0) isLast = (atomicAdd(&d_tick, 1) == (int)gridDim.x - 1);
    __syncthreads();
    if (isLast) {
        if (threadIdx.x < FO) {
            int cc = threadIdx.x;
            float sum = atomicAdd(&d_stats[cc], 0.f);
            float sq  = atomicAdd(&d_stats[128 + cc], 0.f);
            float m   = sum * (1.0f / NN);
            float var = sq * (1.0f / NN) - m * m;
            float scv = gam[cc] * rsqrtf(var + BN_EPS);
            d_scale[cc] = scv;
            d_shift[cc] = bet[cc] - m * scv;
            d_stats[cc] = 0.f;
            d_stats[128 + cc] = 0.f;
        }
        if (threadIdx.x == 0) d_tick = 0;
    }
}

// ---------------- fused max-pool (BN folded) + linear + log_softmax ----------------
__global__ void k_poolhead(const float* __restrict__ Wl, const float* __restrict__ bl,
                           float* __restrict__ out) {
    __shared__ float ssum[12];
    int g = blockIdx.x, t = threadIdx.x;
    float sc = d_scale[t], sh = d_shift[t];
    float m = -CUDART_INF_F;
    int s = d_gstart[g], e = d_gend[g];
    int i = s;
    for (; i + 4 <= e; i += 4) {
        float v0 = d_y3[(size_t)(i + 0) * 128 + t];
        float v1 = d_y3[(size_t)(i + 1) * 128 + t];
        float v2 = d_y3[(size_t)(i + 2) * 128 + t];
        float v3 = d_y3[(size_t)(i + 3) * 128 + t];
        m = fmaxf(m, fmaxf(fmaxf(v0, v1), fmaxf(v2, v3)));
    }
    for (; i < e; i++) m = fmaxf(m, d_y3[(size_t)i * 128 + t]);
    float p = fmaf(m, sc, sh);
    float a0 = p * Wl[t * 3 + 0];
    float a1 = p * Wl[t * 3 + 1];
    float a2 = p * Wl[t * 3 + 2];
#pragma unroll
    for (int o = 16; o > 0; o >>= 1) {
        a0 += __shfl_down_sync(0xFFFFFFFFu, a0, o);
        a1 += __shfl_down_sync(0xFFFFFFFFu, a1, o);
        a2 += __shfl_down_sync(0xFFFFFFFFu, a2, o);
    }
    int w = t >> 5;
    if ((t & 31) == 0) { ssum[w * 3] = a0; ssum[w * 3 + 1] = a1; ssum[w * 3 + 2] = a2; }
    __syncthreads();
    if (t == 0) {
        float l0 = bl[0], l1 = bl[1], l2 = bl[2];
#pragma unroll
        for (int k = 0; k < 4; k++) {
            l0 += ssum[k * 3]; l1 += ssum[k * 3 + 1]; l2 += ssum[k * 3 + 2];
        }
        float mx = fmaxf(l0, fmaxf(l1, l2));
        float lse = mx + logf(expf(l0 - mx) + expf(l1 - mx) + expf(l2 - mx));
        out[g * 3 + 0] = l0 - lse;
        out[g * 3 + 1] = l1 - lse;
        out[g * 3 + 2] = l2 - lse;
    }
}

// ---------------- launcher ----------------
extern "C" void kernel_launch(void* const* d_in, const int* in_sizes, int n_in,
                              void* d_out, int out_size) {
    const float* x   = (const float*)d_in[0];
    const void*  ei  = d_in[1];
    const void*  bi  = d_in[2];
    const float* W1  = (const float*)d_in[3];
    const float* b1  = (const float*)d_in[4];
    const float* g1  = (const float*)d_in[5];
    const float* be1 = (const float*)d_in[6];
    const float* W2  = (const float*)d_in[7];
    const float* b2  = (const float*)d_in[8];
    const float* g2  = (const float*)d_in[9];
    const float* be2 = (const float*)d_in[10];
    const float* W3  = (const float*)d_in[11];
    const float* b3  = (const float*)d_in[12];
    const float* g3  = (const float*)d_in[13];
    const float* be3 = (const float*)d_in[14];
    const float* Wl  = (const float*)d_in[15];
    const float* bl  = (const float*)d_in[16];
    float* out = (float*)d_out;

    // device symbol addresses (host code may NOT use __device__ symbols directly)
    float *y1, *y2, *y3;
    cudaGetSymbolAddress((void**)&y1, d_y1);
    cudaGetSymbolAddress((void**)&y2, d_y2);
    cudaGetSymbolAddress((void**)&y3, d_y3);

    const int T = 256;
    const int EB = (NE + T - 1) / T;
    const int G  = 592;

    k_detect<<<2, 256>>>(ei, bi);
    k_initbounds<<<NBLK, T>>>(bi);

    // CSR build
    k_count<<<EB, T>>>(ei);
    k_scan1<<<NBLK, T>>>();
    k_scan2<<<1, 512>>>();
    k_scan3<<<NBLK, T>>>();
    k_fill<<<EB, T>>>(ei);

    // layer 1: 2 -> 8
    k_l1<<<NBLK, T>>>(x, W1, b1);
    k_stats<8><<<256, T>>>(y1, g1, be1);

    // layer 2: 8 -> 32
    k_l2<<<G, T>>>(W2, b2);
    k_stats<32><<<256, T>>>(y2, g2, be2);

    // layer 3: 32 -> 128
    k_l3<<<G, T>>>(W3, b3);
    k_stats<128><<<256, T>>>(y3, g3, be3);

    // pooling + head
    k_poolhead<<<NG, 128>>>(Wl, bl, out);
}

// round 10
// speedup vs baseline: 1.1152x; 1.1152x over previous
#include <cuda_runtime.h>
#include <math_constants.h>

// ---------------- problem constants ----------------
#define NN 100000      // nodes
#define NE 3200000     // edges
#define NG 512         // graphs
#define BN_EPS 1e-5f
#define NBLK ((NN + 255) / 256)   // 391

typedef unsigned long long ull;

// ---------------- device scratch (no allocs allowed) ----------------
__device__ int    d_cnt[NN];
__device__ int    d_rowptr[NN + 1];
__device__ int    d_wp[NN];
__device__ ull    d_tile[512];            // lookback scan state (flag<<32 | value)
__device__ float2 d_csr[NE];              // (src as int bits, norm)
__device__ float  d_dis[NN];
__device__ float  d_y1 [(size_t)NN * 8];
__device__ float  d_y2 [(size_t)NN * 32];
__device__ float  d_y3 [(size_t)NN * 128];
__device__ float  d_stats[256];           // [0..127] sum, [128..255] sumsq
__device__ float  d_scale[128];
__device__ float  d_shift[128];
__device__ int    d_gstart[NG];
__device__ int    d_gend[NG];
__device__ int    d_is64_edge;
__device__ int    d_is64_batch;
__device__ int    d_tick;

// ---------------- BN finalize epilogue (ticket; last block computes params) ----------------
__device__ __forceinline__ void bn_finalize(int FO, const float* gam, const float* bet) {
    __threadfence();
    __shared__ int isLast;
    if (threadIdx.x == 0) isLast = (atomicAdd(&d_tick, 1) == (int)gridDim.x - 1);
    __syncthreads();
    if (isLast) {
        if ((int)threadIdx.x < FO) {
            int c = threadIdx.x;
            float sum = atomicAdd(&d_stats[c], 0.f);
            float sq  = atomicAdd(&d_stats[128 + c], 0.f);
            float m   = sum * (1.0f / NN);
            float var = sq * (1.0f / NN) - m * m;
            float scv = gam[c] * rsqrtf(var + BN_EPS);
            d_scale[c] = scv;
            d_shift[c] = bet[c] - m * scv;
            d_stats[c] = 0.f;
            d_stats[128 + c] = 0.f;
        }
        if (threadIdx.x == 0) d_tick = 0;
    }
}

// ---------------- prep: zero state + dtype detection ----------------
__global__ void k_prep(const void* ei, const void* bi) {
    int i = blockIdx.x * blockDim.x + threadIdx.x;
    if (i < NN) d_cnt[i] = 0;
    if (i < 512) d_tile[i] = 0ULL;
    if (i < 256) d_stats[i] = 0.f;
    if (i == 0) d_tick = 0;
    if (blockIdx.x == 0) {
        long long v = ((const long long*)ei)[(size_t)threadIdx.x * 6000];
        int ok = (v >= 0 && v < NN);
        ok = __syncthreads_and(ok);
        if (threadIdx.x == 0) d_is64_edge = ok;
    } else if (blockIdx.x == 1) {
        long long v = ((const long long*)bi)[(size_t)threadIdx.x * 195];
        int ok = (v >= 0 && v < NG);
        ok = __syncthreads_and(ok);
        if (threadIdx.x == 0) d_is64_batch = ok;
    }
}

// ---------------- count in-degrees + graph boundaries ----------------
__global__ void k_countbounds(const void* ei, const void* bi) {
    int e = blockIdx.x * blockDim.x + threadIdx.x;
    if (e < NE) {
        int d;
        if (d_is64_edge) d = (int)((const long long*)ei)[(size_t)NE + e];
        else             d = ((const int*)ei)[NE + e];
        atomicAdd(&d_cnt[d], 1);
    }
    if (e < NN) {
        int i = e, g, gp, gn;
        if (d_is64_batch) {
            const long long* p = (const long long*)bi;
            g  = (int)p[i];
            gp = (i > 0)      ? (int)p[i - 1] : -1;
            gn = (i < NN - 1) ? (int)p[i + 1] : NG;
        } else {
            const int* p = (const int*)bi;
            g  = p[i];
            gp = (i > 0)      ? p[i - 1] : -1;
            gn = (i < NN - 1) ? p[i + 1] : NG;
        }
        if (g != gp) d_gstart[g] = i;
        if (g != gn) d_gend[g] = i + 1;
    }
}

// ---------------- single-kernel decoupled-lookback scan ----------------
// All 391 blocks (256 thr) fit co-resident -> spin is deadlock-free.
__global__ void k_scan() {
    __shared__ int s[256];
    __shared__ int sExcl;
    int b = blockIdx.x, t = threadIdx.x;
    int i = b * 256 + t;
    int orig = (i < NN) ? d_cnt[i] : 0;
    s[t] = orig;
    __syncthreads();
    for (int o = 1; o < 256; o <<= 1) {
        int u = (t >= o) ? s[t - o] : 0;
        __syncthreads();
        s[t] += u;
        __syncthreads();
    }
    int incl = s[t];
    int agg  = s[255];
    if (t == 0) {
        if (b == 0) {
            sExcl = 0;
            *(volatile ull*)&d_tile[0] = (2ULL << 32) | (unsigned)agg;
        } else {
            *(volatile ull*)&d_tile[b] = (1ULL << 32) | (unsigned)agg;
            int excl = 0, p = b - 1;
            while (1) {
                ull v;
                do { v = *(volatile ull*)&d_tile[p]; } while ((unsigned)(v >> 32) == 0u);
                excl += (int)(unsigned)v;
                if ((unsigned)(v >> 32) == 2u) break;
                p--;
            }
            *(volatile ull*)&d_tile[b] = (2ULL << 32) | (unsigned)(excl + agg);
            sExcl = excl;
        }
    }
    __syncthreads();
    int ex = sExcl + incl - orig;
    if (i < NN) {
        d_rowptr[i] = ex;
        d_wp[i] = ex;
        d_dis[i] = rsqrtf((float)(orig + 1));
    }
    if (i == 0) d_rowptr[NN] = NE;
}

// ---------------- CSR fill ----------------
__global__ void k_fill(const void* ei) {
    int e = blockIdx.x * blockDim.x + threadIdx.x;
    if (e >= NE) return;
    int s, d;
    if (d_is64_edge) {
        const long long* p = (const long long*)ei;
        s = (int)p[e];
        d = (int)p[(size_t)NE + e];
    } else {
        const int* p = (const int*)ei;
        s = p[e];
        d = p[NE + e];
    }
    int pos = atomicAdd(&d_wp[d], 1);
    d_csr[pos] = make_float2(__int_as_float(s), d_dis[s] * d_dis[d]);
}

// ---------------- layer 1: agg(F=2) + GEMM 2->8 + relu + BN stats ----------------
__global__ void k_l1(const float* __restrict__ x,
                     const float* __restrict__ W1, const float* __restrict__ b1,
                     const float* __restrict__ g1, const float* __restrict__ be1) {
    __shared__ float sW[16], sb[8], sst[32];
    if (threadIdx.x < 16) sW[threadIdx.x] = W1[threadIdx.x];
    if (threadIdx.x < 8)  sb[threadIdx.x] = b1[threadIdx.x];
    if (threadIdx.x < 32) sst[threadIdx.x] = 0.f;
    __syncthreads();
    int i = blockIdx.x * blockDim.x + threadIdx.x;
    bool act = i < NN;
    float o[8];
#pragma unroll
    for (int k = 0; k < 8; k++) o[k] = 0.f;
    if (act) {
        const float2* x2 = (const float2*)x;
        float di = d_dis[i];
        float2 self = x2[i];
        float ax = self.x * di * di, ay = self.y * di * di;
        int e = d_rowptr[i], end = d_rowptr[i + 1];
        for (; e + 4 <= end; e += 4) {
            float2 p0 = __ldg(&d_csr[e]),     p1 = __ldg(&d_csr[e + 1]);
            float2 p2 = __ldg(&d_csr[e + 2]), p3 = __ldg(&d_csr[e + 3]);
            float2 v0 = __ldg(&x2[__float_as_int(p0.x)]);
            float2 v1 = __ldg(&x2[__float_as_int(p1.x)]);
            float2 v2 = __ldg(&x2[__float_as_int(p2.x)]);
            float2 v3 = __ldg(&x2[__float_as_int(p3.x)]);
            ax += v0.x * p0.y + v1.x * p1.y + v2.x * p2.y + v3.x * p3.y;
            ay += v0.y * p0.y + v1.y * p1.y + v2.y * p2.y + v3.y * p3.y;
        }
        for (; e < end; e++) {
            float2 p = __ldg(&d_csr[e]);
            float2 v = __ldg(&x2[__float_as_int(p.x)]);
            ax += v.x * p.y;
            ay += v.y * p.y;
        }
#pragma unroll
        for (int k = 0; k < 8; k++)
            o[k] = fmaxf(fmaf(ax, sW[k], fmaf(ay, sW[8 + k], sb[k])), 0.f);
        float4* yo = (float4*)(d_y1 + (size_t)i * 8);
        yo[0] = make_float4(o[0], o[1], o[2], o[3]);
        yo[1] = make_float4(o[4], o[5], o[6], o[7]);
    }
    // stats: butterfly reduce 8 sums + 8 sqs over warp
#pragma unroll
    for (int k = 0; k < 8; k++) {
        float s = o[k], q = o[k] * o[k];
#pragma unroll
        for (int off = 16; off; off >>= 1) {
            s += __shfl_xor_sync(0xFFFFFFFFu, s, off);
            q += __shfl_xor_sync(0xFFFFFFFFu, q, off);
        }
        if ((threadIdx.x & 31) == 0) {
            atomicAdd(&sst[k], s);
            atomicAdd(&sst[16 + k], q);
        }
    }
    __syncthreads();
    if (threadIdx.x < 8) {
        atomicAdd(&d_stats[threadIdx.x], sst[threadIdx.x]);
        atomicAdd(&d_stats[128 + threadIdx.x], sst[16 + threadIdx.x]);
    }
    bn_finalize(8, g1, be1);
}

// ---------------- layer 2: agg(F=8, BN folded) + GEMM 8->32 + relu + BN stats ----------------
__global__ void k_l2(const float* __restrict__ W2, const float* __restrict__ b2,
                     const float* __restrict__ g2, const float* __restrict__ be2) {
    __shared__ float sW[8 * 32], sb[32], sst[64];
    for (int k = threadIdx.x; k < 256; k += blockDim.x) sW[k] = W2[k];
    if (threadIdx.x < 32) sb[threadIdx.x] = b2[threadIdx.x];
    if (threadIdx.x < 64) sst[threadIdx.x] = 0.f;
    __syncthreads();
    int lane = threadIdx.x & 31;
    int sub  = lane >> 3;
    int ln   = lane & 7;
    int gwarp  = (blockIdx.x * blockDim.x + threadIdx.x) >> 5;
    int nwarps = (gridDim.x * blockDim.x) >> 5;
    float sc = d_scale[ln], sh = d_shift[ln];
    float ls0 = 0.f, ls1 = 0.f, ls2 = 0.f, ls3 = 0.f;
    float lq0 = 0.f, lq1 = 0.f, lq2 = 0.f, lq3 = 0.f;
    for (int n0 = gwarp * 4; n0 < NN; n0 += nwarps * 4) {
        int node = n0 + sub;
        bool act = node < NN;
        int e = 0, end = 0;
        float acc0 = 0.f, acc1 = 0.f;
        if (act) {
            float di = d_dis[node];
            e = d_rowptr[node];
            end = d_rowptr[node + 1];
            acc0 = fmaf(d_y1[(size_t)node * 8 + ln], sc, sh) * di * di;
        }
        for (; e + 8 <= end; e += 8) {
            float2 p0 = __ldg(&d_csr[e]),     p1 = __ldg(&d_csr[e + 1]);
            float2 p2 = __ldg(&d_csr[e + 2]), p3 = __ldg(&d_csr[e + 3]);
            float2 p4 = __ldg(&d_csr[e + 4]), p5 = __ldg(&d_csr[e + 5]);
            float2 p6 = __ldg(&d_csr[e + 6]), p7 = __ldg(&d_csr[e + 7]);
            float h0 = __ldg(&d_y1[(size_t)__float_as_int(p0.x) * 8 + ln]);
            float h1 = __ldg(&d_y1[(size_t)__float_as_int(p1.x) * 8 + ln]);
            float h2 = __ldg(&d_y1[(size_t)__float_as_int(p2.x) * 8 + ln]);
            float h3 = __ldg(&d_y1[(size_t)__float_as_int(p3.x) * 8 + ln]);
            float h4 = __ldg(&d_y1[(size_t)__float_as_int(p4.x) * 8 + ln]);
            float h5 = __ldg(&d_y1[(size_t)__float_as_int(p5.x) * 8 + ln]);
            float h6 = __ldg(&d_y1[(size_t)__float_as_int(p6.x) * 8 + ln]);
            float h7 = __ldg(&d_y1[(size_t)__float_as_int(p7.x) * 8 + ln]);
            acc0 = fmaf(fmaf(h0, sc, sh), p0.y, acc0);
            acc1 = fmaf(fmaf(h1, sc, sh), p1.y, acc1);
            acc0 = fmaf(fmaf(h2, sc, sh), p2.y, acc0);
            acc1 = fmaf(fmaf(h3, sc, sh), p3.y, acc1);
            acc0 = fmaf(fmaf(h4, sc, sh), p4.y, acc0);
            acc1 = fmaf(fmaf(h5, sc, sh), p5.y, acc1);
            acc0 = fmaf(fmaf(h6, sc, sh), p6.y, acc0);
            acc1 = fmaf(fmaf(h7, sc, sh), p7.y, acc1);
        }
        for (; e < end; e++) {
            float2 p = __ldg(&d_csr[e]);
            float hv = __ldg(&d_y1[(size_t)__float_as_int(p.x) * 8 + ln]);
            acc0 = fmaf(fmaf(hv, sc, sh), p.y, acc0);
        }
        float acc = acc0 + acc1;
        float4 yv = make_float4(sb[ln * 4], sb[ln * 4 + 1], sb[ln * 4 + 2], sb[ln * 4 + 3]);
#pragma unroll
        for (int f = 0; f < 8; f++) {
            float av = __shfl_sync(0xFFFFFFFFu, acc, f, 8);
            const float* wr = &sW[f * 32 + ln * 4];
            yv.x = fmaf(av, wr[0], yv.x);
            yv.y = fmaf(av, wr[1], yv.y);
            yv.z = fmaf(av, wr[2], yv.z);
            yv.w = fmaf(av, wr[3], yv.w);
        }
        yv.x = fmaxf(yv.x, 0.f); yv.y = fmaxf(yv.y, 0.f);
        yv.z = fmaxf(yv.z, 0.f); yv.w = fmaxf(yv.w, 0.f);
        if (act) {
            ((float4*)(d_y2 + (size_t)node * 32))[ln] = yv;
            ls0 += yv.x; lq0 += yv.x * yv.x;
            ls1 += yv.y; lq1 += yv.y * yv.y;
            ls2 += yv.z; lq2 += yv.z * yv.z;
            ls3 += yv.w; lq3 += yv.w * yv.w;
        }
    }
    // reduce across the 4 sub-groups (lanes ln, ln+8, ln+16, ln+24)
#pragma unroll
    for (int off = 8; off <= 16; off <<= 1) {
        ls0 += __shfl_xor_sync(0xFFFFFFFFu, ls0, off);
        ls1 += __shfl_xor_sync(0xFFFFFFFFu, ls1, off);
        ls2 += __shfl_xor_sync(0xFFFFFFFFu, ls2, off);
        ls3 += __shfl_xor_sync(0xFFFFFFFFu, ls3, off);
        lq0 += __shfl_xor_sync(0xFFFFFFFFu, lq0, off);
        lq1 += __shfl_xor_sync(0xFFFFFFFFu, lq1, off);
        lq2 += __shfl_xor_sync(0xFFFFFFFFu, lq2, off);
        lq3 += __shfl_xor_sync(0xFFFFFFFFu, lq3, off);
    }
    if (lane < 8) {
        atomicAdd(&sst[ln * 4 + 0], ls0); atomicAdd(&sst[32 + ln * 4 + 0], lq0);
        atomicAdd(&sst[ln * 4 + 1], ls1); atomicAdd(&sst[32 + ln * 4 + 1], lq1);
        atomicAdd(&sst[ln * 4 + 2], ls2); atomicAdd(&sst[32 + ln * 4 + 2], lq2);
        atomicAdd(&sst[ln * 4 + 3], ls3); atomicAdd(&sst[32 + ln * 4 + 3], lq3);
    }
    __syncthreads();
    if (threadIdx.x < 32) {
        atomicAdd(&d_stats[threadIdx.x], sst[threadIdx.x]);
        atomicAdd(&d_stats[128 + threadIdx.x], sst[32 + threadIdx.x]);
    }
    bn_finalize(32, g2, be2);
}

// ---------------- layer 3: agg(F=32, BN folded) + GEMM 32->128 + relu + BN stats ----------------
__global__ void k_l3(const float* __restrict__ W3, const float* __restrict__ b3,
                     const float* __restrict__ g3, const float* __restrict__ be3) {
    __shared__ float4 sW4[32 * 32];
    __shared__ float  sb[128];
    __shared__ float  bs[256];
    for (int k = threadIdx.x; k < 1024; k += blockDim.x)
        sW4[k] = ((const float4*)W3)[k];
    if (threadIdx.x < 128) sb[threadIdx.x] = b3[threadIdx.x];
    bs[threadIdx.x] = 0.f;
    __syncthreads();
    int lane = threadIdx.x & 31;
    int gwarp  = (blockIdx.x * blockDim.x + threadIdx.x) >> 5;
    int nwarps = (gridDim.x * blockDim.x) >> 5;
    float sc = d_scale[lane], sh = d_shift[lane];
    float ls0 = 0.f, ls1 = 0.f, ls2 = 0.f, ls3 = 0.f;
    float lq0 = 0.f, lq1 = 0.f, lq2 = 0.f, lq3 = 0.f;
    for (int node = gwarp; node < NN; node += nwarps) {
        float di = d_dis[node];
        int e = d_rowptr[node], end = d_rowptr[node + 1];
        float acc0 = fmaf(d_y2[(size_t)node * 32 + lane], sc, sh) * di * di;
        float acc1 = 0.f;
        for (; e + 8 <= end; e += 8) {
            float2 p0 = __ldg(&d_csr[e]),     p1 = __ldg(&d_csr[e + 1]);
            float2 p2 = __ldg(&d_csr[e + 2]), p3 = __ldg(&d_csr[e + 3]);
            float2 p4 = __ldg(&d_csr[e + 4]), p5 = __ldg(&d_csr[e + 5]);
            float2 p6 = __ldg(&d_csr[e + 6]), p7 = __ldg(&d_csr[e + 7]);
            float h0 = __ldg(&d_y2[(size_t)__float_as_int(p0.x) * 32 + lane]);
            float h1 = __ldg(&d_y2[(size_t)__float_as_int(p1.x) * 32 + lane]);
            float h2 = __ldg(&d_y2[(size_t)__float_as_int(p2.x) * 32 + lane]);
            float h3 = __ldg(&d_y2[(size_t)__float_as_int(p3.x) * 32 + lane]);
            float h4 = __ldg(&d_y2[(size_t)__float_as_int(p4.x) * 32 + lane]);
            float h5 = __ldg(&d_y2[(size_t)__float_as_int(p5.x) * 32 + lane]);
            float h6 = __ldg(&d_y2[(size_t)__float_as_int(p6.x) * 32 + lane]);
            float h7 = __ldg(&d_y2[(size_t)__float_as_int(p7.x) * 32 + lane]);
            acc0 = fmaf(fmaf(h0, sc, sh), p0.y, acc0);
            acc1 = fmaf(fmaf(h1, sc, sh), p1.y, acc1);
            acc0 = fmaf(fmaf(h2, sc, sh), p2.y, acc0);
            acc1 = fmaf(fmaf(h3, sc, sh), p3.y, acc1);
            acc0 = fmaf(fmaf(h4, sc, sh), p4.y, acc0);
            acc1 = fmaf(fmaf(h5, sc, sh), p5.y, acc1);
            acc0 = fmaf(fmaf(h6, sc, sh), p6.y, acc0);
            acc1 = fmaf(fmaf(h7, sc, sh), p7.y, acc1);
        }
        for (; e < end; e++) {
            float2 p = __ldg(&d_csr[e]);
            float hv = __ldg(&d_y2[(size_t)__float_as_int(p.x) * 32 + lane]);
            acc0 = fmaf(fmaf(hv, sc, sh), p.y, acc0);
        }
        float acc = acc0 + acc1;
        float4 yv = make_float4(sb[lane * 4], sb[lane * 4 + 1],
                                sb[lane * 4 + 2], sb[lane * 4 + 3]);
#pragma unroll
        for (int f = 0; f < 32; f++) {
            float av = __shfl_sync(0xFFFFFFFFu, acc, f);
            float4 w = sW4[f * 32 + lane];
            yv.x = fmaf(av, w.x, yv.x);
            yv.y = fmaf(av, w.y, yv.y);
            yv.z = fmaf(av, w.z, yv.z);
            yv.w = fmaf(av, w.w, yv.w);
        }
        yv.x = fmaxf(yv.x, 0.f); yv.y = fmaxf(yv.y, 0.f);
        yv.z = fmaxf(yv.z, 0.f); yv.w = fmaxf(yv.w, 0.f);
        ((float4*)(d_y3 + (size_t)node * 128))[lane] = yv;
        ls0 += yv.x; lq0 += yv.x * yv.x;
        ls1 += yv.y; lq1 += yv.y * yv.y;
        ls2 += yv.z; lq2 += yv.z * yv.z;
        ls3 += yv.w; lq3 += yv.w * yv.w;
    }
    // lane owns channels lane*4..+3 exclusively within warp; cross-warp via shared
    atomicAdd(&bs[lane * 4 + 0], ls0); atomicAdd(&bs[128 + lane * 4 + 0], lq0);
    atomicAdd(&bs[lane * 4 + 1], ls1); atomicAdd(&bs[128 + lane * 4 + 1], lq1);
    atomicAdd(&bs[lane * 4 + 2], ls2); atomicAdd(&bs[128 + lane * 4 + 2], lq2);
    atomicAdd(&bs[lane * 4 + 3], ls3); atomicAdd(&bs[128 + lane * 4 + 3], lq3);
    __syncthreads();
    atomicAdd(&d_stats[threadIdx.x], bs[threadIdx.x]);
    bn_finalize(128, g3, be3);
}

// ---------------- fused max-pool (BN folded) + linear + log_softmax ----------------
__global__ void k_poolhead(const float* __restrict__ Wl, const float* __restrict__ bl,
                           float* __restrict__ out) {
    __shared__ float ssum[12];
    int g = blockIdx.x, t = threadIdx.x;
    float sc = d_scale[t], sh = d_shift[t];
    float m = -CUDART_INF_F;
    int s = d_gstart[g], e = d_gend[g];
    int i = s;
    for (; i + 4 <= e; i += 4) {
        float v0 = d_y3[(size_t)(i + 0) * 128 + t];
        float v1 = d_y3[(size_t)(i + 1) * 128 + t];
        float v2 = d_y3[(size_t)(i + 2) * 128 + t];
        float v3 = d_y3[(size_t)(i + 3) * 128 + t];
        m = fmaxf(m, fmaxf(fmaxf(v0, v1), fmaxf(v2, v3)));
    }
    for (; i < e; i++) m = fmaxf(m, d_y3[(size_t)i * 128 + t]);
    float p = fmaf(m, sc, sh);
    float a0 = p * Wl[t * 3 + 0];
    float a1 = p * Wl[t * 3 + 1];
    float a2 = p * Wl[t * 3 + 2];
#pragma unroll
    for (int o = 16; o > 0; o >>= 1) {
        a0 += __shfl_down_sync(0xFFFFFFFFu, a0, o);
        a1 += __shfl_down_sync(0xFFFFFFFFu, a1, o);
        a2 += __shfl_down_sync(0xFFFFFFFFu, a2, o);
    }
    int w = t >> 5;
    if ((t & 31) == 0) { ssum[w * 3] = a0; ssum[w * 3 + 1] = a1; ssum[w * 3 + 2] = a2; }
    __syncthreads();
    if (t == 0) {
        float l0 = bl[0], l1 = bl[1], l2 = bl[2];
#pragma unroll
        for (int k = 0; k < 4; k++) {
            l0 += ssum[k * 3]; l1 += ssum[k * 3 + 1]; l2 += ssum[k * 3 + 2];
        }
        float mx = fmaxf(l0, fmaxf(l1, l2));
        float lse = mx + logf(expf(l0 - mx) + expf(l1 - mx) + expf(l2 - mx));
        out[g * 3 + 0] = l0 - lse;
        out[g * 3 + 1] = l1 - lse;
        out[g * 3 + 2] = l2 - lse;
    }
}

// ---------------- launcher (8 kernels) ----------------
extern "C" void kernel_launch(void* const* d_in, const int* in_sizes, int n_in,
                              void* d_out, int out_size) {
    const float* x   = (const float*)d_in[0];
    const void*  ei  = d_in[1];
    const void*  bi  = d_in[2];
    const float* W1  = (const float*)d_in[3];
    const float* b1  = (const float*)d_in[4];
    const float* g1  = (const float*)d_in[5];
    const float* be1 = (const float*)d_in[6];
    const float* W2  = (const float*)d_in[7];
    const float* b2  = (const float*)d_in[8];
    const float* g2  = (const float*)d_in[9];
    const float* be2 = (const float*)d_in[10];
    const float* W3  = (const float*)d_in[11];
    const float* b3  = (const float*)d_in[12];
    const float* g3  = (const float*)d_in[13];
    const float* be3 = (const float*)d_in[14];
    const float* Wl  = (const float*)d_in[15];
    const float* bl  = (const float*)d_in[16];
    float* out = (float*)d_out;

    const int T = 256;
    const int EB = (NE + T - 1) / T;
    const int G  = 592;

    k_prep<<<NBLK, T>>>(ei, bi);
    k_countbounds<<<EB, T>>>(ei, bi);
    k_scan<<<NBLK, T>>>();
    k_fill<<<EB, T>>>(ei);
    k_l1<<<NBLK, T>>>(x, W1, b1, g1, be1);
    k_l2<<<G, T>>>(W2, b2, g2, be2);
    k_l3<<<G, T>>>(W3, b3, g3, be3);
    k_poolhead<<<NG, 128>>>(Wl, bl, out);
}

// round 11
// speedup vs baseline: 1.2523x; 1.1229x over previous
#include <cuda_runtime.h>
#include <math_constants.h>

// ---------------- problem constants ----------------
#define NN 100000      // nodes
#define NE 3200000     // edges
#define NG 512         // graphs
#define BN_EPS 1e-5f
#define NBLK ((NN + 255) / 256)   // 391

typedef unsigned long long ull;

// ---------------- packed f32x2 helpers ----------------
__device__ __forceinline__ ull pack2(float lo, float hi) {
    ull r; asm("mov.b64 %0, {%1, %2};" : "=l"(r) : "f"(lo), "f"(hi)); return r;
}
__device__ __forceinline__ ull dup2(float v) {
    ull r; asm("mov.b64 %0, {%1, %1};" : "=l"(r) : "f"(v)); return r;
}
__device__ __forceinline__ void unpack2(ull v, float& lo, float& hi) {
    asm("mov.b64 {%0, %1}, %2;" : "=f"(lo), "=f"(hi) : "l"(v));
}
__device__ __forceinline__ void ffma2(ull& d, ull a, ull b) {
    asm("fma.rn.f32x2 %0, %1, %2, %0;" : "+l"(d) : "l"(a), "l"(b));
}

// ---------------- device scratch (no allocs allowed) ----------------
__device__ int    d_cnt[NN];
__device__ int    d_rowptr[NN + 1];
__device__ int    d_wp[NN];
__device__ ull    d_tile[512];            // lookback scan state
__device__ float2 d_csr[NE];              // (src as int bits, dis[src])
__device__ float  d_dis[NN];
__device__ float  d_y1 [(size_t)NN * 8];
__device__ float  d_y2 [(size_t)NN * 32];
__device__ float  d_y3 [(size_t)NN * 128];
__device__ float  d_stats[256];
__device__ float  d_scale[128];
__device__ float  d_shift[128];
__device__ int    d_gstart[NG];
__device__ int    d_gend[NG];
__device__ int    d_is64_edge;
__device__ int    d_is64_batch;
__device__ int    d_tick;
__device__ int    d_bar;

// ---------------- BN finalize epilogue ----------------
__device__ __forceinline__ void bn_finalize(int FO, const float* gam, const float* bet) {
    __threadfence();
    __shared__ int isLast;
    if (threadIdx.x == 0) isLast = (atomicAdd(&d_tick, 1) == (int)gridDim.x - 1);
    __syncthreads();
    if (isLast) {
        if ((int)threadIdx.x < FO) {
            int c = threadIdx.x;
            float sum = atomicAdd(&d_stats[c], 0.f);
            float sq  = atomicAdd(&d_stats[128 + c], 0.f);
            float m   = sum * (1.0f / NN);
            float var = sq * (1.0f / NN) - m * m;
            float scv = gam[c] * rsqrtf(var + BN_EPS);
            d_scale[c] = scv;
            d_shift[c] = bet[c] - m * scv;
            d_stats[c] = 0.f;
            d_stats[128 + c] = 0.f;
        }
        if (threadIdx.x == 0) d_tick = 0;
    }
}

// ---------------- prep: zero state + dtype detection ----------------
__global__ void k_prep(const void* ei, const void* bi) {
    int i = blockIdx.x * blockDim.x + threadIdx.x;
    if (i < NN) d_cnt[i] = 0;
    if (i < 512) d_tile[i] = 0ULL;
    if (i < 256) d_stats[i] = 0.f;
    if (i == 0) { d_tick = 0; d_bar = 0; }
    if (blockIdx.x == 0) {
        long long v = ((const long long*)ei)[(size_t)threadIdx.x * 6000];
        int ok = (v >= 0 && v < NN);
        ok = __syncthreads_and(ok);
        if (threadIdx.x == 0) d_is64_edge = ok;
    } else if (blockIdx.x == 1) {
        long long v = ((const long long*)bi)[(size_t)threadIdx.x * 195];
        int ok = (v >= 0 && v < NG);
        ok = __syncthreads_and(ok);
        if (threadIdx.x == 0) d_is64_batch = ok;
    }
}

// ---------------- count in-degrees + graph boundaries ----------------
__global__ void k_countbounds(const void* ei, const void* bi) {
    int e = blockIdx.x * blockDim.x + threadIdx.x;
    if (e < NE) {
        int d;
        if (d_is64_edge) d = (int)((const long long*)ei)[(size_t)NE + e];
        else             d = ((const int*)ei)[NE + e];
        atomicAdd(&d_cnt[d], 1);
    }
    if (e < NN) {
        int i = e, g, gp, gn;
        if (d_is64_batch) {
            const long long* p = (const long long*)bi;
            g  = (int)p[i];
            gp = (i > 0)      ? (int)p[i - 1] : -1;
            gn = (i < NN - 1) ? (int)p[i + 1] : NG;
        } else {
            const int* p = (const int*)bi;
            g  = p[i];
            gp = (i > 0)      ? p[i - 1] : -1;
            gn = (i < NN - 1) ? p[i + 1] : NG;
        }
        if (g != gp) d_gstart[g] = i;
        if (g != gn) d_gend[g] = i + 1;
    }
}

// ---------------- scan (lookback) + grid barrier + CSR fill, one kernel ----------------
__global__ void k_scanfill(const void* ei) {
    __shared__ int s[256];
    __shared__ int sExcl;
    int b = blockIdx.x, t = threadIdx.x;
    int i = b * 256 + t;
    int orig = (i < NN) ? d_cnt[i] : 0;
    s[t] = orig;
    __syncthreads();
    for (int o = 1; o < 256; o <<= 1) {
        int u = (t >= o) ? s[t - o] : 0;
        __syncthreads();
        s[t] += u;
        __syncthreads();
    }
    int incl = s[t];
    int agg  = s[255];
    if (t == 0) {
        if (b == 0) {
            sExcl = 0;
            *(volatile ull*)&d_tile[0] = (2ULL << 32) | (unsigned)agg;
        } else {
            *(volatile ull*)&d_tile[b] = (1ULL << 32) | (unsigned)agg;
            int excl = 0, p = b - 1;
            while (1) {
                ull v;
                do { v = *(volatile ull*)&d_tile[p]; } while ((unsigned)(v >> 32) == 0u);
                excl += (int)(unsigned)v;
                if ((unsigned)(v >> 32) == 2u) break;
                p--;
            }
            *(volatile ull*)&d_tile[b] = (2ULL << 32) | (unsigned)(excl + agg);
            sExcl = excl;
        }
    }
    __syncthreads();
    int ex = sExcl + incl - orig;
    if (i < NN) {
        d_rowptr[i] = ex;
        d_wp[i] = ex;
        d_dis[i] = rsqrtf((float)(orig + 1));
    }
    if (i == 0) d_rowptr[NN] = NE;
    // ---- grid barrier (all 391 blocks co-resident) ----
    __threadfence();
    __syncthreads();
    if (t == 0) {
        atomicAdd(&d_bar, 1);
        while (*(volatile int*)&d_bar < (int)gridDim.x) {}
    }
    __syncthreads();
    __threadfence();
    // ---- fill: csr entry = (src, dis[src]); dis[dst] folded into agg kernels ----
    int stride = gridDim.x * blockDim.x;
    for (int e = b * 256 + t; e < NE; e += stride) {
        int sN, dN;
        if (d_is64_edge) {
            const long long* p = (const long long*)ei;
            sN = (int)p[e];
            dN = (int)p[(size_t)NE + e];
        } else {
            const int* p = (const int*)ei;
            sN = p[e];
            dN = p[NE + e];
        }
        int pos = atomicAdd(&d_wp[dN], 1);
        d_csr[pos] = make_float2(__int_as_float(sN), d_dis[sN]);
    }
}

// ---------------- layer 1: agg(F=2) + GEMM 2->8 + relu + BN stats ----------------
__global__ void k_l1(const float* __restrict__ x,
                     const float* __restrict__ W1, const float* __restrict__ b1,
                     const float* __restrict__ g1, const float* __restrict__ be1) {
    __shared__ float sW[16], sb[8], sst[32];
    if (threadIdx.x < 16) sW[threadIdx.x] = W1[threadIdx.x];
    if (threadIdx.x < 8)  sb[threadIdx.x] = b1[threadIdx.x];
    if (threadIdx.x < 32) sst[threadIdx.x] = 0.f;
    __syncthreads();
    int i = blockIdx.x * blockDim.x + threadIdx.x;
    bool act = i < NN;
    float o[8];
#pragma unroll
    for (int k = 0; k < 8; k++) o[k] = 0.f;
    if (act) {
        const float2* x2 = (const float2*)x;
        float di = d_dis[i];
        float2 self = x2[i];
        float ax = self.x * di, ay = self.y * di;    // agg = di*(di*self + sum dis_s*x_s)
        int e = d_rowptr[i], end = d_rowptr[i + 1];
        for (; e + 4 <= end; e += 4) {
            float2 p0 = __ldg(&d_csr[e]),     p1 = __ldg(&d_csr[e + 1]);
            float2 p2 = __ldg(&d_csr[e + 2]), p3 = __ldg(&d_csr[e + 3]);
            float2 v0 = __ldg(&x2[__float_as_int(p0.x)]);
            float2 v1 = __ldg(&x2[__float_as_int(p1.x)]);
            float2 v2 = __ldg(&x2[__float_as_int(p2.x)]);
            float2 v3 = __ldg(&x2[__float_as_int(p3.x)]);
            ax += v0.x * p0.y + v1.x * p1.y + v2.x * p2.y + v3.x * p3.y;
            ay += v0.y * p0.y + v1.y * p1.y + v2.y * p2.y + v3.y * p3.y;
        }
        for (; e < end; e++) {
            float2 p = __ldg(&d_csr[e]);
            float2 v = __ldg(&x2[__float_as_int(p.x)]);
            ax += v.x * p.y;
            ay += v.y * p.y;
        }
        ax *= di; ay *= di;
#pragma unroll
        for (int k = 0; k < 8; k++)
            o[k] = fmaxf(fmaf(ax, sW[k], fmaf(ay, sW[8 + k], sb[k])), 0.f);
        float4* yo = (float4*)(d_y1 + (size_t)i * 8);
        yo[0] = make_float4(o[0], o[1], o[2], o[3]);
        yo[1] = make_float4(o[4], o[5], o[6], o[7]);
    }
#pragma unroll
    for (int k = 0; k < 8; k++) {
        float s = o[k], q = o[k] * o[k];
#pragma unroll
        for (int off = 16; off; off >>= 1) {
            s += __shfl_xor_sync(0xFFFFFFFFu, s, off);
            q += __shfl_xor_sync(0xFFFFFFFFu, q, off);
        }
        if ((threadIdx.x & 31) == 0) {
            atomicAdd(&sst[k], s);
            atomicAdd(&sst[16 + k], q);
        }
    }
    __syncthreads();
    if (threadIdx.x < 8) {
        atomicAdd(&d_stats[threadIdx.x], sst[threadIdx.x]);
        atomicAdd(&d_stats[128 + threadIdx.x], sst[16 + threadIdx.x]);
    }
    bn_finalize(8, g1, be1);
}

// ---------------- layer 2: agg(F=8, BN folded) + GEMM 8->32 + relu + BN stats ----------------
__global__ void k_l2(const float* __restrict__ W2, const float* __restrict__ b2,
                     const float* __restrict__ g2, const float* __restrict__ be2) {
    __shared__ float sW[8 * 32], sb[32], sst[64];
    for (int k = threadIdx.x; k < 256; k += blockDim.x) sW[k] = W2[k];
    if (threadIdx.x < 32) sb[threadIdx.x] = b2[threadIdx.x];
    if (threadIdx.x < 64) sst[threadIdx.x] = 0.f;
    __syncthreads();
    int lane = threadIdx.x & 31;
    int sub  = lane >> 3;
    int ln   = lane & 7;
    int gwarp  = (blockIdx.x * blockDim.x + threadIdx.x) >> 5;
    int nwarps = (gridDim.x * blockDim.x) >> 5;
    float sc = d_scale[ln], sh = d_shift[ln];
    float ls0 = 0.f, ls1 = 0.f, ls2 = 0.f, ls3 = 0.f;
    float lq0 = 0.f, lq1 = 0.f, lq2 = 0.f, lq3 = 0.f;
    for (int n0 = gwarp * 4; n0 < NN; n0 += nwarps * 4) {
        int node = n0 + sub;
        bool act = node < NN;
        int e = 0, end = 0;
        float acc0 = 0.f, acc1 = 0.f, di = 0.f;
        if (act) {
            di = d_dis[node];
            e = d_rowptr[node];
            end = d_rowptr[node + 1];
            acc0 = fmaf(d_y1[(size_t)node * 8 + ln], sc, sh) * di;
        }
        for (; e + 8 <= end; e += 8) {
            float2 p0 = __ldg(&d_csr[e]),     p1 = __ldg(&d_csr[e + 1]);
            float2 p2 = __ldg(&d_csr[e + 2]), p3 = __ldg(&d_csr[e + 3]);
            float2 p4 = __ldg(&d_csr[e + 4]), p5 = __ldg(&d_csr[e + 5]);
            float2 p6 = __ldg(&d_csr[e + 6]), p7 = __ldg(&d_csr[e + 7]);
            float h0 = __ldg(&d_y1[(size_t)__float_as_int(p0.x) * 8 + ln]);
            float h1 = __ldg(&d_y1[(size_t)__float_as_int(p1.x) * 8 + ln]);
            float h2 = __ldg(&d_y1[(size_t)__float_as_int(p2.x) * 8 + ln]);
            float h3 = __ldg(&d_y1[(size_t)__float_as_int(p3.x) * 8 + ln]);
            float h4 = __ldg(&d_y1[(size_t)__float_as_int(p4.x) * 8 + ln]);
            float h5 = __ldg(&d_y1[(size_t)__float_as_int(p5.x) * 8 + ln]);
            float h6 = __ldg(&d_y1[(size_t)__float_as_int(p6.x) * 8 + ln]);
            float h7 = __ldg(&d_y1[(size_t)__float_as_int(p7.x) * 8 + ln]);
            acc0 = fmaf(fmaf(h0, sc, sh), p0.y, acc0);
            acc1 = fmaf(fmaf(h1, sc, sh), p1.y, acc1);
            acc0 = fmaf(fmaf(h2, sc, sh), p2.y, acc0);
            acc1 = fmaf(fmaf(h3, sc, sh), p3.y, acc1);
            acc0 = fmaf(fmaf(h4, sc, sh), p4.y, acc0);
            acc1 = fmaf(fmaf(h5, sc, sh), p5.y, acc1);
            acc0 = fmaf(fmaf(h6, sc, sh), p6.y, acc0);
            acc1 = fmaf(fmaf(h7, sc, sh), p7.y, acc1);
        }
        for (; e < end; e++) {
            float2 p = __ldg(&d_csr[e]);
            float hv = __ldg(&d_y1[(size_t)__float_as_int(p.x) * 8 + ln]);
            acc0 = fmaf(fmaf(hv, sc, sh), p.y, acc0);
        }
        float acc = (acc0 + acc1) * di;
        float4 yv = make_float4(sb[ln * 4], sb[ln * 4 + 1], sb[ln * 4 + 2], sb[ln * 4 + 3]);
#pragma unroll
        for (int f = 0; f < 8; f++) {
            float av = __shfl_sync(0xFFFFFFFFu, acc, f, 8);
            const float* wr = &sW[f * 32 + ln * 4];
            yv.x = fmaf(av, wr[0], yv.x);
            yv.y = fmaf(av, wr[1], yv.y);
            yv.z = fmaf(av, wr[2], yv.z);
            yv.w = fmaf(av, wr[3], yv.w);
        }
        yv.x = fmaxf(yv.x, 0.f); yv.y = fmaxf(yv.y, 0.f);
        yv.z = fmaxf(yv.z, 0.f); yv.w = fmaxf(yv.w, 0.f);
        if (act) {
            ((float4*)(d_y2 + (size_t)node * 32))[ln] = yv;
            ls0 += yv.x; lq0 += yv.x * yv.x;
            ls1 += yv.y; lq1 += yv.y * yv.y;
            ls2 += yv.z; lq2 += yv.z * yv.z;
            ls3 += yv.w; lq3 += yv.w * yv.w;
        }
    }
#pragma unroll
    for (int off = 8; off <= 16; off <<= 1) {
        ls0 += __shfl_xor_sync(0xFFFFFFFFu, ls0, off);
        ls1 += __shfl_xor_sync(0xFFFFFFFFu, ls1, off);
        ls2 += __shfl_xor_sync(0xFFFFFFFFu, ls2, off);
        ls3 += __shfl_xor_sync(0xFFFFFFFFu, ls3, off);
        lq0 += __shfl_xor_sync(0xFFFFFFFFu, lq0, off);
        lq1 += __shfl_xor_sync(0xFFFFFFFFu, lq1, off);
        lq2 += __shfl_xor_sync(0xFFFFFFFFu, lq2, off);
        lq3 += __shfl_xor_sync(0xFFFFFFFFu, lq3, off);
    }
    if (lane < 8) {
        atomicAdd(&sst[ln * 4 + 0], ls0); atomicAdd(&sst[32 + ln * 4 + 0], lq0);
        atomicAdd(&sst[ln * 4 + 1], ls1); atomicAdd(&sst[32 + ln * 4 + 1], lq1);
        atomicAdd(&sst[ln * 4 + 2], ls2); atomicAdd(&sst[32 + ln * 4 + 2], lq2);
        atomicAdd(&sst[ln * 4 + 3], ls3); atomicAdd(&sst[32 + ln * 4 + 3], lq3);
    }
    __syncthreads();
    if (threadIdx.x < 32) {
        atomicAdd(&d_stats[threadIdx.x], sst[threadIdx.x]);
        atomicAdd(&d_stats[128 + threadIdx.x], sst[32 + threadIdx.x]);
    }
    bn_finalize(32, g2, be2);
}

// ---------------- layer 3: agg + GEMM 32->128 (4-node batched, f32x2) + BN stats ----------------
__global__ void k_l3(const float* __restrict__ W3, const float* __restrict__ b3,
                     const float* __restrict__ g3, const float* __restrict__ be3) {
    __shared__ ull   sW[2048];     // W3 as packed f32x2 pairs: [f][64] (ch pairs)
    __shared__ float sb[128];
    __shared__ float bs[256];
    for (int k = threadIdx.x; k < 2048; k += blockDim.x)
        sW[k] = ((const ull*)W3)[k];
    if (threadIdx.x < 128) sb[threadIdx.x] = b3[threadIdx.x];
    bs[threadIdx.x] = 0.f;
    __syncthreads();
    int lane = threadIdx.x & 31;
    int gwarp  = (blockIdx.x * blockDim.x + threadIdx.x) >> 5;
    int nwarps = (gridDim.x * blockDim.x) >> 5;
    float sc = d_scale[lane], sh = d_shift[lane];
    ull bias01 = pack2(sb[lane * 4], sb[lane * 4 + 1]);
    ull bias23 = pack2(sb[lane * 4 + 2], sb[lane * 4 + 3]);
    float ls0 = 0.f, ls1 = 0.f, ls2 = 0.f, ls3 = 0.f;
    float lq0 = 0.f, lq1 = 0.f, lq2 = 0.f, lq3 = 0.f;
    for (int n0 = gwarp * 4; n0 < NN; n0 += nwarps * 4) {
        // ---- aggregate 4 nodes ----
        float accs[4];
#pragma unroll
        for (int nb = 0; nb < 4; nb++) {
            int node = n0 + nb;
            float acc0 = 0.f, acc1 = 0.f, di = 0.f;
            if (node < NN) {
                di = d_dis[node];
                int e = d_rowptr[node], end = d_rowptr[node + 1];
                acc0 = fmaf(d_y2[(size_t)node * 32 + lane], sc, sh) * di;
                for (; e + 8 <= end; e += 8) {
                    float2 p0 = __ldg(&d_csr[e]),     p1 = __ldg(&d_csr[e + 1]);
                    float2 p2 = __ldg(&d_csr[e + 2]), p3 = __ldg(&d_csr[e + 3]);
                    float2 p4 = __ldg(&d_csr[e + 4]), p5 = __ldg(&d_csr[e + 5]);
                    float2 p6 = __ldg(&d_csr[e + 6]), p7 = __ldg(&d_csr[e + 7]);
                    float h0 = __ldg(&d_y2[(size_t)__float_as_int(p0.x) * 32 + lane]);
                    float h1 = __ldg(&d_y2[(size_t)__float_as_int(p1.x) * 32 + lane]);
                    float h2 = __ldg(&d_y2[(size_t)__float_as_int(p2.x) * 32 + lane]);
                    float h3 = __ldg(&d_y2[(size_t)__float_as_int(p3.x) * 32 + lane]);
                    float h4 = __ldg(&d_y2[(size_t)__float_as_int(p4.x) * 32 + lane]);
                    float h5 = __ldg(&d_y2[(size_t)__float_as_int(p5.x) * 32 + lane]);
                    float h6 = __ldg(&d_y2[(size_t)__float_as_int(p6.x) * 32 + lane]);
                    float h7 = __ldg(&d_y2[(size_t)__float_as_int(p7.x) * 32 + lane]);
                    acc0 = fmaf(fmaf(h0, sc, sh), p0.y, acc0);
                    acc1 = fmaf(fmaf(h1, sc, sh), p1.y, acc1);
                    acc0 = fmaf(fmaf(h2, sc, sh), p2.y, acc0);
                    acc1 = fmaf(fmaf(h3, sc, sh), p3.y, acc1);
                    acc0 = fmaf(fmaf(h4, sc, sh), p4.y, acc0);
                    acc1 = fmaf(fmaf(h5, sc, sh), p5.y, acc1);
                    acc0 = fmaf(fmaf(h6, sc, sh), p6.y, acc0);
                    acc1 = fmaf(fmaf(h7, sc, sh), p7.y, acc1);
                }
                for (; e < end; e++) {
                    float2 p = __ldg(&d_csr[e]);
                    float hv = __ldg(&d_y2[(size_t)__float_as_int(p.x) * 32 + lane]);
                    acc0 = fmaf(fmaf(hv, sc, sh), p.y, acc0);
                }
            }
            accs[nb] = (acc0 + acc1) * di;
        }
        // ---- GEMM 32->128 for 4 nodes: weight row loaded once per 4 nodes ----
        ull a01[4], a23[4];
#pragma unroll
        for (int nb = 0; nb < 4; nb++) { a01[nb] = bias01; a23[nb] = bias23; }
#pragma unroll
        for (int f = 0; f < 32; f++) {
            ull w01 = sW[f * 64 + lane * 2];
            ull w23 = sW[f * 64 + lane * 2 + 1];
#pragma unroll
            for (int nb = 0; nb < 4; nb++) {
                ull avv = dup2(__shfl_sync(0xFFFFFFFFu, accs[nb], f));
                ffma2(a01[nb], avv, w01);
                ffma2(a23[nb], avv, w23);
            }
        }
#pragma unroll
        for (int nb = 0; nb < 4; nb++) {
            int node = n0 + nb;
            if (node >= NN) break;
            float v0, v1, v2, v3;
            unpack2(a01[nb], v0, v1);
            unpack2(a23[nb], v2, v3);
            v0 = fmaxf(v0, 0.f); v1 = fmaxf(v1, 0.f);
            v2 = fmaxf(v2, 0.f); v3 = fmaxf(v3, 0.f);
            ((float4*)(d_y3 + (size_t)node * 128))[lane] = make_float4(v0, v1, v2, v3);
            ls0 += v0; lq0 += v0 * v0;
            ls1 += v1; lq1 += v1 * v1;
            ls2 += v2; lq2 += v2 * v2;
            ls3 += v3; lq3 += v3 * v3;
        }
    }
    atomicAdd(&bs[lane * 4 + 0], ls0); atomicAdd(&bs[128 + lane * 4 + 0], lq0);
    atomicAdd(&bs[lane * 4 + 1], ls1); atomicAdd(&bs[128 + lane * 4 + 1], lq1);
    atomicAdd(&bs[lane * 4 + 2], ls2); atomicAdd(&bs[128 + lane * 4 + 2], lq2);
    atomicAdd(&bs[lane * 4 + 3], ls3); atomicAdd(&bs[128 + lane * 4 + 3], lq3);
    __syncthreads();
    atomicAdd(&d_stats[threadIdx.x], bs[threadIdx.x]);
    bn_finalize(128, g3, be3);
}

// ---------------- fused max-pool (BN folded) + linear + log_softmax ----------------
__global__ void k_poolhead(const float* __restrict__ Wl, const float* __restrict__ bl,
                           float* __restrict__ out) {
    __shared__ float ssum[12];
    int g = blockIdx.x, t = threadIdx.x;
    float sc = d_scale[t], sh = d_shift[t];
    float m = -CUDART_INF_F;
    int s = d_gstart[g], e = d_gend[g];
    int i = s;
    for (; i + 4 <= e; i += 4) {
        float v0 = d_y3[(size_t)(i + 0) * 128 + t];
        float v1 = d_y3[(size_t)(i + 1) * 128 + t];
        float v2 = d_y3[(size_t)(i + 2) * 128 + t];
        float v3 = d_y3[(size_t)(i + 3) * 128 + t];
        m = fmaxf(m, fmaxf(fmaxf(v0, v1), fmaxf(v2, v3)));
    }
    for (; i < e; i++) m = fmaxf(m, d_y3[(size_t)i * 128 + t]);
    float p = fmaf(m, sc, sh);
    float a0 = p * Wl[t * 3 + 0];
    float a1 = p * Wl[t * 3 + 1];
    float a2 = p * Wl[t * 3 + 2];
#pragma unroll
    for (int o = 16; o > 0; o >>= 1) {
        a0 += __shfl_down_sync(0xFFFFFFFFu, a0, o);
        a1 += __shfl_down_sync(0xFFFFFFFFu, a1, o);
        a2 += __shfl_down_sync(0xFFFFFFFFu, a2, o);
    }
    int w = t >> 5;
    if ((t & 31) == 0) { ssum[w * 3] = a0; ssum[w * 3 + 1] = a1; ssum[w * 3 + 2] = a2; }
    __syncthreads();
    if (t == 0) {
        float l0 = bl[0], l1 = bl[1], l2 = bl[2];
#pragma unroll
        for (int k = 0; k < 4; k++) {
            l0 += ssum[k * 3]; l1 += ssum[k * 3 + 1]; l2 += ssum[k * 3 + 2];
        }
        float mx = fmaxf(l0, fmaxf(l1, l2));
        float lse = mx + logf(expf(l0 - mx) + expf(l1 - mx) + expf(l2 - mx));
        out[g * 3 + 0] = l0 - lse;
        out[g * 3 + 1] = l1 - lse;
        out[g * 3 + 2] = l2 - lse;
    }
}

// ---------------- launcher (7 kernels) ----------------
extern "C" void kernel_launch(void* const* d_in, const int* in_sizes, int n_in,
                              void* d_out, int out_size) {
    const float* x   = (const float*)d_in[0];
    const void*  ei  = d_in[1];
    const void*  bi  = d_in[2];
    const float* W1  = (const float*)d_in[3];
    const float* b1  = (const float*)d_in[4];
    const float* g1  = (const float*)d_in[5];
    const float* be1 = (const float*)d_in[6];
    const float* W2  = (const float*)d_in[7];
    const float* b2  = (const float*)d_in[8];
    const float* g2  = (const float*)d_in[9];
    const float* be2 = (const float*)d_in[10];
    const float* W3  = (const float*)d_in[11];
    const float* b3  = (const float*)d_in[12];
    const float* g3  = (const float*)d_in[13];
    const float* be3 = (const float*)d_in[14];
    const float* Wl  = (const float*)d_in[15];
    const float* bl  = (const float*)d_in[16];
    float* out = (float*)d_out;

    const int T = 256;
    const int EB = (NE + T - 1) / T;
    const int G  = 592;

    k_prep<<<NBLK, T>>>(ei, bi);
    k_countbounds<<<EB, T>>>(ei, bi);
    k_scanfill<<<NBLK, T>>>(ei);
    k_l1<<<NBLK, T>>>(x, W1, b1, g1, be1);
    k_l2<<<G, T>>>(W2, b2, g2, be2);
    k_l3<<<G, T>>>(W3, b3, g3, be3);
    k_poolhead<<<NG, 128>>>(Wl, bl, out);
}